// round 16
// baseline (speedup 1.0000x reference)
#include <cuda_runtime.h>
#include <math.h>

#define T 8192
#define D 4096
#define E 8
#define KSEL 2
#define SLOTS (T * KSEL)
#define NHB 64             // rank blocks
#define SPB (SLOTS / NHB)  // 256 slots per rank block
#define SGRID 592          // 4 quarters x 148
#define NG4 (T / 4)        // 2048 token groups
#define XT4 2048           // float4 offset of x rings in smem
#define SMEMF4 (XT4 + 16 * 256)   // 6144 float4 = 96KB per block

// Output layout (float32, concatenated in reference-return order)
#define OFF_XG  0
#define OFF_CNT 67108864ll   // 16384*4096
#define OFF_IDX 67108872ll
#define OFF_SC  67125256ll

// Scratch (no allocations allowed -> __device__ globals)
__device__ float g_part[4 * T * E];   // [quarter][token][expert] partials, 1MB
__device__ int   g_pos[SLOTS];
__device__ int   g_bhist[NHB * E];
__device__ volatile int g_sync;  // rank kernel global barrier (self-resetting)
__device__ int   g_done;

// L2 evict_last access policy (keeps x resident for the scatter pass)
__device__ __forceinline__ unsigned long long mk_policy_el() {
    unsigned long long p;
    asm("createpolicy.fractional.L2::evict_last.b64 %0, 1.0;" : "=l"(p));
    return p;
}
__device__ __forceinline__ void cp16(unsigned saddr, const float* g,
                                     unsigned long long pol) {
    asm volatile("cp.async.cg.shared.global.L2::cache_hint [%0], [%1], 16, %2;"
                 :: "r"(saddr), "l"(g), "l"(pol));
}

// ---------------------------------------------------------------------------
// Kernel A: router partial scores (quarter-D blocks).
// grid = 592 = 4 quarters x 148. Block stages its 32KB W-quarter in smem
// (96KB total with rings -> 2 blocks/SM -> 27.7 ACTIVE warps/SM, 2x before).
// Warp task: 4 tokens x quarter-D, 8 iterations of 128 floats/row,
// 2-stage cp.async ring (2KB stages). Writes 32-float partial per task.
// ---------------------------------------------------------------------------
extern __shared__ float4 Ws[];   // [0,2048): W quarter; [2048,6144): x rings

__global__ void __launch_bounds__(512, 2) router_scores_kernel(
    const float* __restrict__ x, const float* __restrict__ W)
{
    const int tid  = threadIdx.x;
    const int w    = tid >> 5;
    const int lane = tid & 31;
    const int qd   = blockIdx.x / 148;   // D-quarter
    const int rb   = blockIdx.x % 148;

    const float4* __restrict__ w4 = (const float4*)W;

    // stage W quarter: 2048 float4 (32KB), 4 per thread
#pragma unroll
    for (int k = 0; k < 4; k++) {
        const int m = tid + k * 512;     // 0..2047
        const int e = m >> 8;
        const int i = m & 255;
        Ws[m] = w4[e * 1024 + qd * 256 + i];
    }
    __syncthreads();

    const int g = w * 148 + rb;
    if (g >= NG4) return;
    const int t0 = g * 4;

    const unsigned long long pol = mk_policy_el();
    const float* __restrict__ xbase = x + (size_t)t0 * D + qd * 1024;

    // this warp's 2-stage ring: float4 [slot][row][lane], slot stride 128
    float4* xs = Ws + XT4 + w * 256;
    const unsigned swarp =
        (unsigned)__cvta_generic_to_shared(xs) + (unsigned)(lane * 16);

#define ISSUE(slot, it)                                                    \
    {                                                                      \
        _Pragma("unroll")                                                  \
        for (int q = 0; q < 4; q++) {                                      \
            unsigned sa = swarp + (unsigned)(((slot) * 128 + q * 32) * 16);\
            const float* ga = xbase + q * D + (it) * 128 + lane * 4;       \
            cp16(sa, ga, pol);                                             \
        }                                                                  \
        asm volatile("cp.async.commit_group;");                            \
    }

    ISSUE(0, 0); ISSUE(1, 1);

    float acc[4][E];
#pragma unroll
    for (int j = 0; j < 4; j++)
#pragma unroll
        for (int e = 0; e < E; e++) acc[j][e] = 0.f;

#pragma unroll
    for (int it = 0; it < 8; it++) {
        asm volatile("cp.async.wait_group 1;");

        const float4* st = xs + (it & 1) * 128;
        float4 xv0 = st[lane];
        float4 xv1 = st[32 + lane];
        float4 xv2 = st[64 + lane];
        float4 xv3 = st[96 + lane];

        if (it + 2 < 8) {
            ISSUE(it & 1, it + 2);
        } else {
            asm volatile("cp.async.commit_group;");
        }

        const int wb = it * 32 + lane;
#pragma unroll
        for (int e = 0; e < E; e++) {
            float4 wv = Ws[e * 256 + wb];
            acc[0][e] += xv0.x * wv.x + xv0.y * wv.y + xv0.z * wv.z + xv0.w * wv.w;
            acc[1][e] += xv1.x * wv.x + xv1.y * wv.y + xv1.z * wv.z + xv1.w * wv.w;
            acc[2][e] += xv2.x * wv.x + xv2.y * wv.y + xv2.z * wv.z + xv2.w * wv.w;
            acc[3][e] += xv3.x * wv.x + xv3.y * wv.y + xv3.z * wv.z + xv3.w * wv.w;
        }
    }
#undef ISSUE

    // warp tree-reduce 32 scalars (all lanes end with all totals)
#pragma unroll
    for (int off = 16; off > 0; off >>= 1) {
#pragma unroll
        for (int j = 0; j < 4; j++)
#pragma unroll
            for (int e = 0; e < E; e++)
                acc[j][e] += __shfl_xor_sync(0xffffffffu, acc[j][e], off);
    }

    // lane (j*8+e) writes partial for (token t0+j, expert e): one coalesced
    // 128B store per warp
    float v = 0.f;
#pragma unroll
    for (int j = 0; j < 4; j++)
#pragma unroll
        for (int e = 0; e < E; e++)
            if (lane == j * 8 + e) v = acc[j][e];
    g_part[(size_t)qd * T * E + (size_t)t0 * E + lane] = v;
}

// ---------------------------------------------------------------------------
// Packed per-expert counters: 8 experts x 8-bit fields across two uints.
// ---------------------------------------------------------------------------
__device__ __forceinline__ void packAdd(int e, unsigned& lo, unsigned& hi) {
    if (e < 4) lo += 1u << (8 * e);
    else       hi += 1u << (8 * (e - 4));
}
__device__ __forceinline__ int fieldOf(unsigned lo, unsigned hi, int e) {
    unsigned v = (e < 4) ? lo : hi;
    return (int)((v >> (8 * (e & 3))) & 0xffu);
}

// ---------------------------------------------------------------------------
// Kernel B: fused rank. Pre-phase: reduce the 4 quarter-partials, top-2 +
// softmax (deterministic order). Then hist + global barrier + finalize.
// 64 blocks x 256; all co-resident -> spin barrier safe; self-resetting.
// ---------------------------------------------------------------------------
__global__ void __launch_bounds__(SPB) rank_kernel(float* __restrict__ out)
{
    __shared__ int   sexp[SPB];
    __shared__ float sprob[SPB];
    __shared__ unsigned wlo[8], whi[8];
    __shared__ int offE[E], totE[E], baseE[E];

    const int b    = blockIdx.x;
    const int tid  = threadIdx.x;
    const int wid  = tid >> 5;
    const int lane = tid & 31;
    const int slot = b * SPB + tid;

    // ---- phase 0: reduce quarters, top-2, softmax (128 tokens/block) ----
    if (tid < 128) {
        const int t = b * 128 + tid;
        float s[E];
#pragma unroll
        for (int e = 0; e < E; e++) s[e] = 0.f;
#pragma unroll
        for (int qd = 0; qd < 4; qd++) {
            const float4* p4 =
                (const float4*)(g_part + (size_t)qd * T * E + (size_t)t * E);
            float4 a = p4[0], c = p4[1];
            s[0] += a.x; s[1] += a.y; s[2] += a.z; s[3] += a.w;
            s[4] += c.x; s[5] += c.y; s[6] += c.z; s[7] += c.w;
        }
        // stable top-2 (first occurrence wins ties, matching jax.lax.top_k)
        float b0 = -3.4e38f, b1 = -3.4e38f;
        int i0 = 0, i1 = 0;
#pragma unroll
        for (int e = 0; e < E; e++) {
            float v = s[e];
            if (v > b0) { b1 = b0; i1 = i0; b0 = v; i0 = e; }
            else if (v > b1) { b1 = v; i1 = e; }
        }
        float ex = expf(b1 - b0);
        float inv = 1.f / (1.f + ex);
        sexp[2 * tid]      = i0;
        sexp[2 * tid + 1]  = i1;
        sprob[2 * tid]     = inv;
        sprob[2 * tid + 1] = ex * inv;
    }
    __syncthreads();

    // ---- phase 1: local stable rank + per-block histogram ----
    const int e = sexp[tid];
    unsigned lo = 0, hi = 0;
    packAdd(e, lo, hi);
    const unsigned mlo = lo, mhi = hi;

#pragma unroll
    for (int off = 1; off < 32; off <<= 1) {
        unsigned vlo = __shfl_up_sync(0xffffffffu, lo, off);
        unsigned vhi = __shfl_up_sync(0xffffffffu, hi, off);
        if (lane >= off) { lo += vlo; hi += vhi; }
    }
    if (lane == 31) { wlo[wid] = lo; whi[wid] = hi; }
    __syncthreads();

    unsigned plo = 0, phi = 0;
#pragma unroll
    for (int w2 = 0; w2 < 8; w2++)
        if (w2 < wid) { plo += wlo[w2]; phi += whi[w2]; }

    const int lrank = fieldOf(plo + lo - mlo, phi + hi - mhi, e);

    if (tid < E) {
        unsigned tlo = 0, thi = 0;
#pragma unroll
        for (int w2 = 0; w2 < 8; w2++) { tlo += wlo[w2]; thi += whi[w2]; }
        g_bhist[b * E + tid] = fieldOf(tlo, thi, tid);
    }

    // ---- global barrier across the 64 blocks ----
    __threadfence();
    __syncthreads();
    if (tid == 0) atomicAdd((int*)&g_sync, 1);
    if (tid == 0) while (g_sync < NHB) { }
    __syncthreads();
    __threadfence();

    // ---- phase 2: finalize ----
    if (tid < E) {
        int off = 0, tot = 0;
#pragma unroll
        for (int bb = 0; bb < NHB; bb++) {
            int h = g_bhist[bb * E + tid];
            if (bb < b) off += h;
            tot += h;
        }
        offE[tid] = off; totE[tid] = tot;
    }
    __syncthreads();
    if (tid == 0) {
        int s = 0;
#pragma unroll
        for (int ee = 0; ee < E; ee++) { baseE[ee] = s; s += totE[ee]; }
    }
    __syncthreads();

    const int pos = baseE[e] + offE[e] + lrank;
    g_pos[slot] = pos;
    out[OFF_IDX + pos] = (float)(slot >> 1);   // scatter_indices
    out[OFF_SC  + pos] = sprob[tid];           // scores_sorted

    if (b == 0 && tid < E) out[OFF_CNT + tid] = (float)totE[tid];

    // ---- self-reset for next graph replay ----
    __syncthreads();
    if (tid == 0) {
        int d = atomicAdd(&g_done, 1);
        if (d == NHB - 1) { g_sync = 0; g_done = 0; }
    }
}

// ---------------------------------------------------------------------------
// Kernel C: scatter copy — read each token row once, write 2 destination rows.
// ---------------------------------------------------------------------------
__global__ void __launch_bounds__(256) scatter_kernel(
    const float* __restrict__ x, float* __restrict__ out)
{
    const int t = blockIdx.x;
    const int p0 = g_pos[2 * t];
    const int p1 = g_pos[2 * t + 1];
    const float4* __restrict__ src = (const float4*)x + (size_t)t * 1024;
    float4* __restrict__ d0 = (float4*)(out + OFF_XG) + (size_t)p0 * 1024;
    float4* __restrict__ d1 = (float4*)(out + OFF_XG) + (size_t)p1 * 1024;

    const int i = threadIdx.x;
    float4 v0 = __ldcs(src + i);
    float4 v1 = __ldcs(src + i + 256);
    float4 v2 = __ldcs(src + i + 512);
    float4 v3 = __ldcs(src + i + 768);
    __stcs(d0 + i,       v0);
    __stcs(d0 + i + 256, v1);
    __stcs(d0 + i + 512, v2);
    __stcs(d0 + i + 768, v3);
    __stcs(d1 + i,       v0);
    __stcs(d1 + i + 256, v1);
    __stcs(d1 + i + 512, v2);
    __stcs(d1 + i + 768, v3);
}

extern "C" void kernel_launch(void* const* d_in, const int* in_sizes, int n_in,
                              void* d_out, int out_size)
{
    const float* x = (const float*)d_in[0];
    const float* W = (const float*)d_in[1];
    if (n_in >= 2 && in_sizes[0] == E * D && in_sizes[1] == (int)((size_t)T * D)) {
        const float* tmp = x; x = W; W = tmp;
    }
    float* out = (float*)d_out;

    static int smem_set = 0;
    if (!smem_set) {
        cudaFuncSetAttribute(router_scores_kernel,
                             cudaFuncAttributeMaxDynamicSharedMemorySize,
                             SMEMF4 * (int)sizeof(float4));
        smem_set = 1;
    }

    router_scores_kernel<<<SGRID, 512, SMEMF4 * sizeof(float4)>>>(x, W);
    rank_kernel<<<NHB, SPB>>>(out);
    scatter_kernel<<<T, 256>>>(x, out);
}

// round 17
// speedup vs baseline: 1.0500x; 1.0500x over previous
#include <cuda_runtime.h>
#include <math.h>

#define T 8192
#define D 4096
#define E 8
#define KSEL 2
#define SLOTS (T * KSEL)
#define NHB 64             // rank blocks
#define SPB (SLOTS / NHB)  // 256 slots per rank block

// Output layout (float32, concatenated in reference-return order)
#define OFF_XG  0
#define OFF_CNT 67108864ll   // 16384*4096
#define OFF_IDX 67108872ll
#define OFF_SC  67125256ll

// Scratch (no allocations allowed -> __device__ globals)
__device__ float g_part[4 * T * E];   // [quarter][token][expert] partials, 1MB
__device__ int   g_pos[SLOTS];
__device__ int   g_bhist[NHB * E];
__device__ volatile int g_sync;  // rank kernel global barrier (self-resetting)
__device__ int   g_done;

// L2 evict_last access policy (keeps x resident for the scatter pass)
__device__ __forceinline__ unsigned long long mk_policy_el() {
    unsigned long long p;
    asm("createpolicy.fractional.L2::evict_last.b64 %0, 1.0;" : "=l"(p));
    return p;
}
__device__ __forceinline__ float4 ldg_el(const float4* p, unsigned long long pol) {
    float4 v;
    asm("ld.global.L2::cache_hint.v4.f32 {%0,%1,%2,%3}, [%4], %5;"
        : "=f"(v.x), "=f"(v.y), "=f"(v.z), "=f"(v.w) : "l"(p), "l"(pol));
    return v;
}

// ---------------------------------------------------------------------------
// Kernel A: router partial scores (quarter-D blocks, x in registers).
// grid = 1024 = 256 group-bases x 4 quarters. 256 threads (8 warps),
// 32KB W-quarter in smem, 4 blocks/SM -> 32 warps/SM with ~1.7 waves of
// work-steal balance. Warp task: 4 tokens x quarter-D, 8 iterations,
// x via LDG.128 (evict_last), W via conflict-free LDS.128.
// Tail: 31-shfl pairwise-merge butterfly (lane m ends with (token m>>3,
// expert m&7) total) -> one coalesced 128B partial store per warp.
// ---------------------------------------------------------------------------
extern __shared__ float4 Ws[];   // [e * 256 + i], 32KB

__global__ void __launch_bounds__(256, 4) router_scores_kernel(
    const float* __restrict__ x, const float* __restrict__ W)
{
    const int tid  = threadIdx.x;
    const int w    = tid >> 5;
    const int lane = tid & 31;
    const int qd   = blockIdx.x & 3;
    const int gb   = blockIdx.x >> 2;      // 0..255

    const float4* __restrict__ w4 = (const float4*)W;
    const float4* __restrict__ x4 = (const float4*)x;

    // stage W quarter: 2048 float4 (32KB), 8 per thread, coalesced
#pragma unroll
    for (int k = 0; k < 8; k++) {
        const int m = tid + k * 256;       // 0..2047
        const int e = m >> 8;
        const int i = m & 255;
        Ws[m] = w4[e * 1024 + qd * 256 + i];
    }
    __syncthreads();

    const int g  = gb * 8 + w;             // 0..2047, every warp active
    const int t0 = g * 4;

    const unsigned long long pol = mk_policy_el();
    const float4* __restrict__ xr0 = x4 + (size_t)t0 * 1024 + qd * 256;
    const float4* __restrict__ xr1 = xr0 + 1024;
    const float4* __restrict__ xr2 = xr0 + 2048;
    const float4* __restrict__ xr3 = xr0 + 3072;

    float acc[4][E];
#pragma unroll
    for (int j = 0; j < 4; j++)
#pragma unroll
        for (int e = 0; e < E; e++) acc[j][e] = 0.f;

#pragma unroll 2
    for (int it = 0; it < 8; it++) {
        const int i = it * 32 + lane;      // 0..255 within quarter
        float4 xv0 = ldg_el(xr0 + i, pol);
        float4 xv1 = ldg_el(xr1 + i, pol);
        float4 xv2 = ldg_el(xr2 + i, pol);
        float4 xv3 = ldg_el(xr3 + i, pol);
#pragma unroll
        for (int e = 0; e < E; e++) {
            float4 wv = Ws[e * 256 + i];
            acc[0][e] += xv0.x * wv.x + xv0.y * wv.y + xv0.z * wv.z + xv0.w * wv.w;
            acc[1][e] += xv1.x * wv.x + xv1.y * wv.y + xv1.z * wv.z + xv1.w * wv.w;
            acc[2][e] += xv2.x * wv.x + xv2.y * wv.y + xv2.z * wv.z + xv2.w * wv.w;
            acc[3][e] += xv3.x * wv.x + xv3.y * wv.y + xv3.z * wv.z + xv3.w * wv.w;
        }
    }

    // pairwise-merge butterfly: 31 shfl total; lane m ends with the full
    // sum for flattened index m (token j = m>>3, expert e = m&7)
    float v32[32];
#pragma unroll
    for (int j = 0; j < 4; j++)
#pragma unroll
        for (int e = 0; e < E; e++) v32[j * 8 + e] = acc[j][e];

    float v16[16];
#pragma unroll
    for (int m = 0; m < 16; m++) {
        float a = v32[m], b = v32[m + 16];
        float keepv = (lane & 16) ? b : a;
        float sendv = (lane & 16) ? a : b;
        v16[m] = keepv + __shfl_xor_sync(0xffffffffu, sendv, 16);
    }
    float v8[8];
#pragma unroll
    for (int m = 0; m < 8; m++) {
        float a = v16[m], b = v16[m + 8];
        float keepv = (lane & 8) ? b : a;
        float sendv = (lane & 8) ? a : b;
        v8[m] = keepv + __shfl_xor_sync(0xffffffffu, sendv, 8);
    }
    float v4[4];
#pragma unroll
    for (int m = 0; m < 4; m++) {
        float a = v8[m], b = v8[m + 4];
        float keepv = (lane & 4) ? b : a;
        float sendv = (lane & 4) ? a : b;
        v4[m] = keepv + __shfl_xor_sync(0xffffffffu, sendv, 4);
    }
    float v2[2];
#pragma unroll
    for (int m = 0; m < 2; m++) {
        float a = v4[m], b = v4[m + 2];
        float keepv = (lane & 2) ? b : a;
        float sendv = (lane & 2) ? a : b;
        v2[m] = keepv + __shfl_xor_sync(0xffffffffu, sendv, 2);
    }
    float res;
    {
        float a = v2[0], b = v2[1];
        float keepv = (lane & 1) ? b : a;
        float sendv = (lane & 1) ? a : b;
        res = keepv + __shfl_xor_sync(0xffffffffu, sendv, 1);
    }

    // one coalesced 128B store per warp
    g_part[(size_t)qd * T * E + (size_t)t0 * E + lane] = res;
}

// ---------------------------------------------------------------------------
// Packed per-expert counters: 8 experts x 8-bit fields across two uints.
// ---------------------------------------------------------------------------
__device__ __forceinline__ void packAdd(int e, unsigned& lo, unsigned& hi) {
    if (e < 4) lo += 1u << (8 * e);
    else       hi += 1u << (8 * (e - 4));
}
__device__ __forceinline__ int fieldOf(unsigned lo, unsigned hi, int e) {
    unsigned v = (e < 4) ? lo : hi;
    return (int)((v >> (8 * (e & 3))) & 0xffu);
}

// ---------------------------------------------------------------------------
// Kernel B: fused rank. Pre-phase: reduce the 4 quarter-partials, top-2 +
// softmax (deterministic order). Then hist + global barrier + finalize.
// 64 blocks x 256; all co-resident -> spin barrier safe; self-resetting.
// ---------------------------------------------------------------------------
__global__ void __launch_bounds__(SPB) rank_kernel(float* __restrict__ out)
{
    __shared__ int   sexp[SPB];
    __shared__ float sprob[SPB];
    __shared__ unsigned wlo[8], whi[8];
    __shared__ int offE[E], totE[E], baseE[E];

    const int b    = blockIdx.x;
    const int tid  = threadIdx.x;
    const int wid  = tid >> 5;
    const int lane = tid & 31;
    const int slot = b * SPB + tid;

    // ---- phase 0: reduce quarters, top-2, softmax (128 tokens/block) ----
    if (tid < 128) {
        const int t = b * 128 + tid;
        float s[E];
#pragma unroll
        for (int e = 0; e < E; e++) s[e] = 0.f;
#pragma unroll
        for (int qd = 0; qd < 4; qd++) {
            const float4* p4 =
                (const float4*)(g_part + (size_t)qd * T * E + (size_t)t * E);
            float4 a = p4[0], c = p4[1];
            s[0] += a.x; s[1] += a.y; s[2] += a.z; s[3] += a.w;
            s[4] += c.x; s[5] += c.y; s[6] += c.z; s[7] += c.w;
        }
        // stable top-2 (first occurrence wins ties, matching jax.lax.top_k)
        float b0 = -3.4e38f, b1 = -3.4e38f;
        int i0 = 0, i1 = 0;
#pragma unroll
        for (int e = 0; e < E; e++) {
            float v = s[e];
            if (v > b0) { b1 = b0; i1 = i0; b0 = v; i0 = e; }
            else if (v > b1) { b1 = v; i1 = e; }
        }
        float ex = expf(b1 - b0);
        float inv = 1.f / (1.f + ex);
        sexp[2 * tid]      = i0;
        sexp[2 * tid + 1]  = i1;
        sprob[2 * tid]     = inv;
        sprob[2 * tid + 1] = ex * inv;
    }
    __syncthreads();

    // ---- phase 1: local stable rank + per-block histogram ----
    const int e = sexp[tid];
    unsigned lo = 0, hi = 0;
    packAdd(e, lo, hi);
    const unsigned mlo = lo, mhi = hi;

#pragma unroll
    for (int off = 1; off < 32; off <<= 1) {
        unsigned vlo = __shfl_up_sync(0xffffffffu, lo, off);
        unsigned vhi = __shfl_up_sync(0xffffffffu, hi, off);
        if (lane >= off) { lo += vlo; hi += vhi; }
    }
    if (lane == 31) { wlo[wid] = lo; whi[wid] = hi; }
    __syncthreads();

    unsigned plo = 0, phi = 0;
#pragma unroll
    for (int w2 = 0; w2 < 8; w2++)
        if (w2 < wid) { plo += wlo[w2]; phi += whi[w2]; }

    const int lrank = fieldOf(plo + lo - mlo, phi + hi - mhi, e);

    if (tid < E) {
        unsigned tlo = 0, thi = 0;
#pragma unroll
        for (int w2 = 0; w2 < 8; w2++) { tlo += wlo[w2]; thi += whi[w2]; }
        g_bhist[b * E + tid] = fieldOf(tlo, thi, tid);
    }

    // ---- global barrier across the 64 blocks ----
    __threadfence();
    __syncthreads();
    if (tid == 0) atomicAdd((int*)&g_sync, 1);
    if (tid == 0) while (g_sync < NHB) { }
    __syncthreads();
    __threadfence();

    // ---- phase 2: finalize ----
    if (tid < E) {
        int off = 0, tot = 0;
#pragma unroll
        for (int bb = 0; bb < NHB; bb++) {
            int h = g_bhist[bb * E + tid];
            if (bb < b) off += h;
            tot += h;
        }
        offE[tid] = off; totE[tid] = tot;
    }
    __syncthreads();
    if (tid == 0) {
        int s = 0;
#pragma unroll
        for (int ee = 0; ee < E; ee++) { baseE[ee] = s; s += totE[ee]; }
    }
    __syncthreads();

    const int pos = baseE[e] + offE[e] + lrank;
    g_pos[slot] = pos;
    out[OFF_IDX + pos] = (float)(slot >> 1);   // scatter_indices
    out[OFF_SC  + pos] = sprob[tid];           // scores_sorted

    if (b == 0 && tid < E) out[OFF_CNT + tid] = (float)totE[tid];

    // ---- self-reset for next graph replay ----
    __syncthreads();
    if (tid == 0) {
        int d = atomicAdd(&g_done, 1);
        if (d == NHB - 1) { g_sync = 0; g_done = 0; }
    }
}

// ---------------------------------------------------------------------------
// Kernel C: scatter copy — read each token row once, write 2 destination rows.
// ---------------------------------------------------------------------------
__global__ void __launch_bounds__(256) scatter_kernel(
    const float* __restrict__ x, float* __restrict__ out)
{
    const int t = blockIdx.x;
    const int p0 = g_pos[2 * t];
    const int p1 = g_pos[2 * t + 1];
    const float4* __restrict__ src = (const float4*)x + (size_t)t * 1024;
    float4* __restrict__ d0 = (float4*)(out + OFF_XG) + (size_t)p0 * 1024;
    float4* __restrict__ d1 = (float4*)(out + OFF_XG) + (size_t)p1 * 1024;

    const int i = threadIdx.x;
    float4 v0 = __ldcs(src + i);
    float4 v1 = __ldcs(src + i + 256);
    float4 v2 = __ldcs(src + i + 512);
    float4 v3 = __ldcs(src + i + 768);
    __stcs(d0 + i,       v0);
    __stcs(d0 + i + 256, v1);
    __stcs(d0 + i + 512, v2);
    __stcs(d0 + i + 768, v3);
    __stcs(d1 + i,       v0);
    __stcs(d1 + i + 256, v1);
    __stcs(d1 + i + 512, v2);
    __stcs(d1 + i + 768, v3);
}

extern "C" void kernel_launch(void* const* d_in, const int* in_sizes, int n_in,
                              void* d_out, int out_size)
{
    const float* x = (const float*)d_in[0];
    const float* W = (const float*)d_in[1];
    if (n_in >= 2 && in_sizes[0] == E * D && in_sizes[1] == (int)((size_t)T * D)) {
        const float* tmp = x; x = W; W = tmp;
    }
    float* out = (float*)d_out;

    static int smem_set = 0;
    if (!smem_set) {
        cudaFuncSetAttribute(router_scores_kernel,
                             cudaFuncAttributeMaxDynamicSharedMemorySize,
                             2048 * (int)sizeof(float4));
        smem_set = 1;
    }

    router_scores_kernel<<<1024, 256, 2048 * sizeof(float4)>>>(x, W);
    rank_kernel<<<NHB, SPB>>>(out);
    scatter_kernel<<<T, 256>>>(x, out);
}